// round 6
// baseline (speedup 1.0000x reference)
#include <cuda_runtime.h>
#include <cuda_bf16.h>
#include <cstdint>

// TensorDLT closed-form solve for fixed source corners
// (0,0),(127,0),(127,127),(0,127). 8 fp32 in -> 9 fp32 out per element.
//
//   h2 = u1', h5 = v1'
//   a_i = (u_i'-u1')/127, c_i = (v1'-v_i')/127
//   2x2:  (u2'-u3') h6 + (u4'-u3') h7 = a3-a2-a4
//         (v3'-v2') h6 + (v3'-v4') h7 = c3-c2-c4
//   h0 = u2' h6 + a2, h1 = u4' h7 + a4, h3 = v2' h6 - c2, h4 = v4' h7 - c4
//
// R6: persistent CTAs + depth-3 TMA input pipeline + double-buffered TMA
// output with deferred drain. All input loads for a CTA are in flight at
// once; store completion overlaps subsequent tiles. The SM only does
// LDS -> ~30 FMA -> STS per element.

#define BLOCK   256
#define STAGES  3
#define OUTBUF  2
#define MAXGRID 740   // 5 CTAs/SM * 148 SMs

__device__ __forceinline__ uint32_t smem_u32(const void* p) {
    uint32_t a;
    asm("{ .reg .u64 t; cvta.to.shared.u64 t, %1; cvt.u32.u64 %0, t; }"
        : "=r"(a) : "l"(p));
    return a;
}

__device__ __forceinline__ float frcp_approx(float x) {
    float r;
    asm("rcp.approx.f32 %0, %1;" : "=f"(r) : "f"(x));
    return r;
}

__device__ __forceinline__ void mbar_wait(uint32_t mbar, uint32_t parity) {
    asm volatile(
        "{\n\t"
        ".reg .pred P;\n\t"
        "WAIT_%=: \n\t"
        "mbarrier.try_wait.parity.acquire.cta.shared::cta.b64 P, [%0], %1, 0x989680;\n\t"
        "@P bra.uni DONE_%=;\n\t"
        "bra.uni WAIT_%=;\n\t"
        "DONE_%=: \n\t"
        "}"
        :: "r"(mbar), "r"(parity) : "memory");
}

__device__ __forceinline__ void tma_load(uint32_t sdst, const float* gsrc,
                                         uint32_t bytes, uint32_t mbar) {
    asm volatile(
        "mbarrier.arrive.expect_tx.shared.b64 _, [%0], %1;"
        :: "r"(mbar), "r"(bytes) : "memory");
    asm volatile(
        "cp.async.bulk.shared::cluster.global.mbarrier::complete_tx::bytes "
        "[%0], [%1], %2, [%3];"
        :: "r"(sdst), "l"(gsrc), "r"(bytes), "r"(mbar) : "memory");
}

__global__ void __launch_bounds__(BLOCK) tensor_dlt_kernel(
    const float* __restrict__ offset,  // [B, 8]
    float* __restrict__ out,           // [B, 9]
    int B)
{
    __shared__ __align__(16) float sin_[STAGES][BLOCK * 8];   // 24 KB
    __shared__ __align__(16) float sout[OUTBUF][BLOCK * 9];   // 18 KB
    __shared__ __align__(8)  uint64_t mbar[STAGES];

    const int tid    = threadIdx.x;
    const int ntiles = (B + BLOCK - 1) / BLOCK;
    const int bid    = blockIdx.x;
    const int G      = gridDim.x;
    const int myN    = (bid < ntiles) ? ((ntiles - 1 - bid) / G + 1) : 0;

    if (tid < STAGES)
        asm volatile("mbarrier.init.shared.b64 [%0], 1;"
                     :: "r"(smem_u32(&mbar[tid])) : "memory");
    __syncthreads();

    // Prefetch: issue ALL (up to STAGES) input loads immediately.
    if (tid == 0) {
        const int np = myN < STAGES ? myN : STAGES;
        for (int k = 0; k < np; ++k) {
            const int base = (bid + k * G) * BLOCK;
            const int cnt  = min(BLOCK, B - base);
            tma_load(smem_u32(sin_[k]), offset + (size_t)base * 8,
                     (uint32_t)cnt * 32u, smem_u32(&mbar[k]));
        }
    }

    for (int k = 0; k < myN; ++k) {
        const int s      = k % STAGES;
        const uint32_t parity = (uint32_t)((k / STAGES) & 1);
        const int base   = (bid + k * G) * BLOCK;
        const int valid  = min(BLOCK, B - base);
        float* ob = sout[k & 1];

        mbar_wait(smem_u32(&mbar[s]), parity);

        float4 o0, o1;
        if (tid < valid) {
            const float4* pin = reinterpret_cast<const float4*>(sin_[s]) + tid * 2;
            o0 = pin[0];
            o1 = pin[1];
        }

        // Out-buffer reuse: group for tile k-2 must have finished reading.
        if (k >= OUTBUF) {
            if (tid == 0)
                asm volatile("cp.async.bulk.wait_group.read 1;" ::: "memory");
            __syncthreads();
        }

        if (tid < valid) {
            const float up1 =   0.0f + 32.0f * o0.x;
            const float vp1 =   0.0f + 32.0f * o0.y;
            const float up2 = 127.0f + 32.0f * o0.z;
            const float vp2 =   0.0f + 32.0f * o0.w;
            const float up3 = 127.0f + 32.0f * o1.x;
            const float vp3 = 127.0f + 32.0f * o1.y;
            const float up4 =   0.0f + 32.0f * o1.z;
            const float vp4 = 127.0f + 32.0f * o1.w;

            const float inv127 = 1.0f / 127.0f;
            const float a2 = (up2 - up1) * inv127;
            const float a3 = (up3 - up1) * inv127;
            const float a4 = (up4 - up1) * inv127;
            const float c2 = (vp1 - vp2) * inv127;
            const float c3 = (vp1 - vp3) * inv127;
            const float c4 = (vp1 - vp4) * inv127;

            const float m00 = up2 - up3;
            const float m01 = up4 - up3;
            const float m10 = vp3 - vp2;
            const float m11 = vp3 - vp4;
            const float r0 = a3 - a2 - a4;
            const float r1 = c3 - c2 - c4;

            // det ~ +127^2 for |perturbation|<=32 -> well-conditioned.
            const float invdet = frcp_approx(m00 * m11 - m01 * m10);
            const float h6 = (r0 * m11 - m01 * r1) * invdet;
            const float h7 = (m00 * r1 - r0 * m10) * invdet;

            // stride-9 STS: gcd(9,32)=1 -> bank-conflict-free
            float* row = ob + tid * 9;
            row[0] = up2 * h6 + a2;
            row[1] = up4 * h7 + a4;
            row[2] = up1;
            row[3] = vp2 * h6 - c2;
            row[4] = vp4 * h7 - c4;
            row[5] = vp1;
            row[6] = h6;
            row[7] = h7;
            row[8] = 1.0f;
        }
        __syncthreads();

        float* dst = out + (size_t)base * 9;
        if (valid == BLOCK) {
            if (tid == 0) {
                asm volatile("fence.proxy.async.shared::cta;" ::: "memory");
                asm volatile(
                    "cp.async.bulk.global.shared::cta.bulk_group [%0], [%1], %2;"
                    :: "l"(dst), "r"(smem_u32(ob)), "n"(BLOCK * 9 * 4)
                    : "memory");
                asm volatile("cp.async.bulk.commit_group;" ::: "memory");
            }
        } else {
            // Partial tail tile: plain coalesced stores.
            const int n = valid * 9;
            for (int i = tid; i < n; i += BLOCK)
                dst[i] = ob[i];
        }

        // Refill this input stage for tile k+STAGES (all LDS reads for
        // stage s completed before the barrier above).
        if (tid == 0 && k + STAGES < myN) {
            const int nb  = (bid + (k + STAGES) * G) * BLOCK;
            const int ncv = min(BLOCK, B - nb);
            tma_load(smem_u32(sin_[s]), offset + (size_t)nb * 8,
                     (uint32_t)ncv * 32u, smem_u32(&mbar[s]));
        }
    }

    // Drain pending bulk stores before CTA exit frees SMEM.
    if (tid == 0 && myN > 0)
        asm volatile("cp.async.bulk.wait_group.read 0;" ::: "memory");
}

extern "C" void kernel_launch(void* const* d_in, const int* in_sizes, int n_in,
                              void* d_out, int out_size)
{
    const float* offset = (const float*)d_in[0];
    float* out = (float*)d_out;
    const int B = in_sizes[0] / 8;
    const int ntiles = (B + BLOCK - 1) / BLOCK;
    const int grid = ntiles < MAXGRID ? ntiles : MAXGRID;
    tensor_dlt_kernel<<<grid, BLOCK>>>(offset, out, B);
}